// round 5
// baseline (speedup 1.0000x reference)
#include <cuda_runtime.h>
#include <cstdint>

#define N_NODES 4096
#define F_IN    512
#define HD1     64
#define NH1     8
#define C2      16
#define MAXDEG  128

__device__ int   g_nbr[N_NODES * MAXDEG];
__device__ int   g_deg[N_NODES];
__device__ float g_h1 [N_NODES * HD1];
__device__ float g_es1[N_NODES * NH1];
__device__ float g_ed1[N_NODES * NH1];
__device__ float g_h2 [N_NODES * C2];
__device__ float g_es2[N_NODES];
__device__ float g_ed2[N_NODES];

// ---------------------------------------------------------------------------
// K1: adjacency scan -> neighbor lists. 1 block/row, 256 thr, low-reg,
// 4 independent 16B loads/thread issued up front. One __syncthreads.
// ---------------------------------------------------------------------------
__global__ __launch_bounds__(256) void k_scan(const void* __restrict__ adj)
{
    const int i    = blockIdx.x;
    const int tid  = threadIdx.x;
    const int lane = tid & 31;
    const int wid  = tid >> 5;
    const uint8_t* u8 = (const uint8_t*)adj;

    // layout via self-loop adj[1][1]==1 : bool8 / int32 / float32
    int fmt;
    if (u8[(size_t)N_NODES + 1] == 1)            fmt = 0;
    else if (u8[4 * ((size_t)N_NODES + 1)] == 1) fmt = 1;
    else                                         fmt = 2;

    uint32_t mask = 0;   // 16 bits: 4 rounds x 4 elems
    #pragma unroll
    for (int r = 0; r < 4; r++) {
        const int cbase = (r * 256 + tid) * 4;
        uint32_t p0, p1, p2, p3;
        if (fmt == 2) {
            float4 v = *(const float4*)((const float*)adj + (size_t)i * N_NODES + cbase);
            p0 = v.x != 0.f; p1 = v.y != 0.f; p2 = v.z != 0.f; p3 = v.w != 0.f;
        } else if (fmt == 1) {
            int4 v = *(const int4*)((const int*)adj + (size_t)i * N_NODES + cbase);
            p0 = v.x != 0; p1 = v.y != 0; p2 = v.z != 0; p3 = v.w != 0;
        } else {
            uint32_t w = *(const uint32_t*)(u8 + (size_t)i * N_NODES + cbase);
            p0 = (w & 0x000000FFu) != 0;
            p1 = (w & 0x0000FF00u) != 0;
            p2 = (w & 0x00FF0000u) != 0;
            p3 = (w & 0xFF000000u) != 0;
        }
        mask |= (p0 << (r * 4)) | (p1 << (r * 4 + 1)) |
                (p2 << (r * 4 + 2)) | (p3 << (r * 4 + 3));
    }
    const int cnt = __popc(mask);

    // block scan (one sync)
    int incl = cnt;
    #pragma unroll
    for (int o = 1; o < 32; o <<= 1) {
        int t = __shfl_up_sync(0xFFFFFFFFu, incl, o);
        if (lane >= o) incl += t;
    }
    __shared__ int wsum[8];
    if (lane == 31) wsum[wid] = incl;
    __syncthreads();
    int wpre = 0, total = 0;
    #pragma unroll
    for (int wq = 0; wq < 8; wq++) {
        int t = wsum[wq];
        if (wq < wid) wpre += t;
        total += t;
    }
    if (tid == 0) g_deg[i] = (total > MAXDEG) ? MAXDEG : total;

    int base = wpre + (incl - cnt);
    int* out = g_nbr + (size_t)i * MAXDEG;
    #pragma unroll
    for (int r = 0; r < 4; r++) {
        const int cbase = (r * 256 + tid) * 4;
        #pragma unroll
        for (int q = 0; q < 4; q++) {
            if ((mask >> (r * 4 + q)) & 1u) {
                if (base < MAXDEG) out[base] = cbase + q;
                base++;
            }
        }
    }
}

// ---------------------------------------------------------------------------
// K2: GEMM1 h1 = x @ W1 (4096x512 * 512x64), M-tile 32 -> 128 blocks.
// Fused es1/ed1 epilogue via shfl pair-reduction.
// ---------------------------------------------------------------------------
__global__ __launch_bounds__(256) void k_gemm1(const float* __restrict__ X,
                                               const float* __restrict__ W,
                                               const float* __restrict__ a_src,
                                               const float* __restrict__ a_dst)
{
    __shared__ float As[32][33];
    __shared__ float Bs[32][64];

    const int tid = threadIdx.x;
    const int tx  = tid & 15;
    const int ty  = tid >> 4;
    const int m0  = blockIdx.x * 32;

    float acc[2][4] = {};

    for (int kt = 0; kt < F_IN; kt += 32) {
        {
            int r  = tid >> 3;
            int c4 = tid & 7;
            float4 v = *(const float4*)(X + (size_t)(m0 + r) * F_IN + kt + c4 * 4);
            As[c4 * 4 + 0][r] = v.x;
            As[c4 * 4 + 1][r] = v.y;
            As[c4 * 4 + 2][r] = v.z;
            As[c4 * 4 + 3][r] = v.w;
        }
        #pragma unroll
        for (int it = 0; it < 2; it++) {
            int id = tid + it * 256;
            int r  = id >> 4;
            int c4 = id & 15;
            *(float4*)(&Bs[r][c4 * 4]) =
                *(const float4*)(W + (size_t)(kt + r) * HD1 + c4 * 4);
        }
        __syncthreads();
        #pragma unroll
        for (int k = 0; k < 32; k++) {
            float a0 = As[k][ty * 2 + 0];
            float a1 = As[k][ty * 2 + 1];
            float4 b = *(const float4*)(&Bs[k][tx * 4]);
            acc[0][0] += a0 * b.x; acc[0][1] += a0 * b.y;
            acc[0][2] += a0 * b.z; acc[0][3] += a0 * b.w;
            acc[1][0] += a1 * b.x; acc[1][1] += a1 * b.y;
            acc[1][2] += a1 * b.z; acc[1][3] += a1 * b.w;
        }
        __syncthreads();
    }

    #pragma unroll
    for (int u = 0; u < 2; u++) {
        float4 v = make_float4(acc[u][0], acc[u][1], acc[u][2], acc[u][3]);
        *(float4*)(g_h1 + (size_t)(m0 + ty * 2 + u) * HD1 + tx * 4) = v;
    }

    float4 ws = *(const float4*)(a_src + tx * 4);
    float4 wd = *(const float4*)(a_dst + tx * 4);
    float s0 = acc[0][0]*ws.x + acc[0][1]*ws.y + acc[0][2]*ws.z + acc[0][3]*ws.w;
    float s1 = acc[1][0]*ws.x + acc[1][1]*ws.y + acc[1][2]*ws.z + acc[1][3]*ws.w;
    float d0 = acc[0][0]*wd.x + acc[0][1]*wd.y + acc[0][2]*wd.z + acc[0][3]*wd.w;
    float d1 = acc[1][0]*wd.x + acc[1][1]*wd.y + acc[1][2]*wd.z + acc[1][3]*wd.w;
    s0 += __shfl_xor_sync(0xFFFFFFFFu, s0, 1);
    s1 += __shfl_xor_sync(0xFFFFFFFFu, s1, 1);
    d0 += __shfl_xor_sync(0xFFFFFFFFu, d0, 1);
    d1 += __shfl_xor_sync(0xFFFFFFFFu, d1, 1);
    if ((tx & 1) == 0) {
        int h = tx >> 1;
        g_es1[(m0 + ty * 2 + 0) * NH1 + h] = s0;
        g_es1[(m0 + ty * 2 + 1) * NH1 + h] = s1;
        g_ed1[(m0 + ty * 2 + 0) * NH1 + h] = d0;
        g_ed1[(m0 + ty * 2 + 1) * NH1 + h] = d1;
    }
}

// ---------------------------------------------------------------------------
// K3: layer-1 attention + ELU + fused layer-2 row GEMM & scores.
// 2 rows per 128-thread block; halves decoupled by named barriers.
// ---------------------------------------------------------------------------
#define HBAR() asm volatile("bar.sync %0, 64;" :: "r"(half + 1) : "memory")

__global__ __launch_bounds__(128) void k_attn1(const float* __restrict__ W2,
                                               const float* __restrict__ a2_src,
                                               const float* __restrict__ a2_dst)
{
    const int half = threadIdx.x >> 6;
    const int tid  = threadIdx.x & 63;
    const int i    = blockIdx.x * 2 + half;
    const int deg  = g_deg[i];

    __shared__ int   snbr[2][MAXDEG];
    __shared__ float ew  [2][MAXDEG * NH1];
    __shared__ float red [2][2][NH1];
    __shared__ float ssv [2][NH1];
    __shared__ float sesi[2][NH1];
    __shared__ float sa1 [2][HD1];

    for (int j = tid; j < deg; j += 64)
        snbr[half][j] = g_nbr[(size_t)i * MAXDEG + j];
    if (tid < NH1) sesi[half][tid] = g_es1[i * NH1 + tid];
    HBAR();

    const int h  = tid & 7;
    const int wh = tid >> 5;
    const int tot = deg * NH1;
    const float esi_h = sesi[half][h];

    float mloc = -1e30f;
    for (int idx = tid; idx < tot; idx += 64) {
        int j = idx >> 3;
        float e = esi_h + g_ed1[snbr[half][j] * NH1 + h];
        e = (e > 0.f) ? e : 0.2f * e;
        ew[half][idx] = e;
        mloc = fmaxf(mloc, e);
    }
    mloc = fmaxf(mloc, __shfl_xor_sync(0xFFFFFFFFu, mloc, 8));
    mloc = fmaxf(mloc, __shfl_xor_sync(0xFFFFFFFFu, mloc, 16));
    if ((tid & 31) < 8) red[half][wh][tid & 7] = mloc;
    HBAR();
    const float m = fmaxf(red[half][0][h], red[half][1][h]);

    float sloc = 0.f;
    for (int idx = tid; idx < tot; idx += 64) {
        float w = __expf(ew[half][idx] - m);
        ew[half][idx] = w;
        sloc += w;
    }
    sloc += __shfl_xor_sync(0xFFFFFFFFu, sloc, 8);
    sloc += __shfl_xor_sync(0xFFFFFFFFu, sloc, 16);
    if ((tid & 31) < 8) red[half][wh][tid & 7] = sloc;
    HBAR();
    if (tid < NH1) ssv[half][tid] = 1.f / (red[half][0][tid] + red[half][1][tid]);
    HBAR();

    {
        const int hh = tid >> 3;
        const float inv = ssv[half][hh];
        float a0 = 0.f, a1 = 0.f, a2 = 0.f, a3 = 0.f;
        int j = 0;
        for (; j + 4 <= deg; j += 4) {
            a0 += ew[half][(j+0) * NH1 + hh] * g_h1[(size_t)snbr[half][j+0] * HD1 + tid];
            a1 += ew[half][(j+1) * NH1 + hh] * g_h1[(size_t)snbr[half][j+1] * HD1 + tid];
            a2 += ew[half][(j+2) * NH1 + hh] * g_h1[(size_t)snbr[half][j+2] * HD1 + tid];
            a3 += ew[half][(j+3) * NH1 + hh] * g_h1[(size_t)snbr[half][j+3] * HD1 + tid];
        }
        for (; j < deg; j++)
            a0 += ew[half][j * NH1 + hh] * g_h1[(size_t)snbr[half][j] * HD1 + tid];
        float acc = ((a0 + a1) + (a2 + a3)) * inv;
        acc = (acc > 0.f) ? acc : expm1f(acc);   // ELU
        sa1[half][tid] = acc;
    }
    HBAR();

    if (tid < C2) {
        float v = 0.f;
        #pragma unroll 8
        for (int k = 0; k < HD1; k++)
            v += sa1[half][k] * __ldg(&W2[k * C2 + tid]);
        g_h2[(size_t)i * C2 + tid] = v;

        float s = v * a2_src[tid];
        float d = v * a2_dst[tid];
        #pragma unroll
        for (int o = 8; o >= 1; o >>= 1) {
            s += __shfl_xor_sync(0x0000FFFFu, s, o);
            d += __shfl_xor_sync(0x0000FFFFu, d, o);
        }
        if (tid == 0) {
            g_es2[i] = s;
            g_ed2[i] = d;
        }
    }
}

// ---------------------------------------------------------------------------
// K4: layer-2 sparse attention. 4 rows per 128-thread block, 1 warp/row.
// ---------------------------------------------------------------------------
__global__ __launch_bounds__(128) void k_attn2(float* __restrict__ out)
{
    const int w    = threadIdx.x >> 5;
    const int lane = threadIdx.x & 31;
    const int i    = blockIdx.x * 4 + w;
    const int deg  = g_deg[i];

    __shared__ int   snbr[4][MAXDEG];
    __shared__ float ew  [4][MAXDEG];

    for (int j = lane; j < deg; j += 32)
        snbr[w][j] = g_nbr[(size_t)i * MAXDEG + j];
    __syncwarp();

    const float esi = g_es2[i];
    float mloc = -1e30f;
    for (int j = lane; j < deg; j += 32) {
        float e = esi + g_ed2[snbr[w][j]];
        e = (e > 0.f) ? e : 0.2f * e;
        ew[w][j] = e;
        mloc = fmaxf(mloc, e);
    }
    #pragma unroll
    for (int o = 16; o >= 1; o >>= 1)
        mloc = fmaxf(mloc, __shfl_xor_sync(0xFFFFFFFFu, mloc, o));
    __syncwarp();

    float sloc = 0.f;
    for (int j = lane; j < deg; j += 32) {
        float v = __expf(ew[w][j] - mloc);
        ew[w][j] = v;
        sloc += v;
    }
    #pragma unroll
    for (int o = 16; o >= 1; o >>= 1)
        sloc += __shfl_xor_sync(0xFFFFFFFFu, sloc, o);
    const float inv = 1.f / sloc;
    __syncwarp();

    if (lane < C2) {
        float a0 = 0.f, a1 = 0.f, a2 = 0.f, a3 = 0.f;
        int j = 0;
        for (; j + 4 <= deg; j += 4) {
            a0 += ew[w][j+0] * g_h2[(size_t)snbr[w][j+0] * C2 + lane];
            a1 += ew[w][j+1] * g_h2[(size_t)snbr[w][j+1] * C2 + lane];
            a2 += ew[w][j+2] * g_h2[(size_t)snbr[w][j+2] * C2 + lane];
            a3 += ew[w][j+3] * g_h2[(size_t)snbr[w][j+3] * C2 + lane];
        }
        for (; j < deg; j++)
            a0 += ew[w][j] * g_h2[(size_t)snbr[w][j] * C2 + lane];
        out[(size_t)i * C2 + lane] = ((a0 + a1) + (a2 + a3)) * inv;
    }
}

// ---------------------------------------------------------------------------
extern "C" void kernel_launch(void* const* d_in, const int* in_sizes, int n_in,
                              void* d_out, int out_size)
{
    const float* x      = (const float*)d_in[0];
    const void*  adj    = d_in[1];
    const float* W1     = (const float*)d_in[2];
    const float* a1_src = (const float*)d_in[3];
    const float* a1_dst = (const float*)d_in[4];
    const float* W2     = (const float*)d_in[5];
    const float* a2_src = (const float*)d_in[6];
    const float* a2_dst = (const float*)d_in[7];
    float* out = (float*)d_out;

    k_scan <<<N_NODES, 256>>>(adj);
    k_gemm1<<<N_NODES / 32, 256>>>(x, W1, a1_src, a1_dst);
    k_attn1<<<N_NODES / 2, 128>>>(W2, a2_src, a2_dst);
    k_attn2<<<N_NODES / 4, 128>>>(out);
}

// round 6
// speedup vs baseline: 1.2521x; 1.2521x over previous
#include <cuda_runtime.h>
#include <cstdint>

#define N_NODES 4096
#define F_IN    512
#define HD1     64
#define NH1     8
#define C2      16
#define MAXDEG  256

__device__ int   g_nbr[N_NODES * MAXDEG];
__device__ int   g_deg[N_NODES];
__device__ float g_h1 [N_NODES * HD1];
__device__ float g_es1[N_NODES * NH1];
__device__ float g_ed1[N_NODES * NH1];
__device__ float g_h2 [N_NODES * C2];
__device__ float g_es2[N_NODES];
__device__ float g_ed2[N_NODES];

// ---------------------------------------------------------------------------
// K1: adjacency scan -> neighbor lists. 1 block/row, 128 thr, 8 independent
// 16B loads per thread (MLP=8), one block scan, one __syncthreads.
// (exact round-3 shape — the fastest measured so far)
// ---------------------------------------------------------------------------
__global__ __launch_bounds__(128) void k_scan(const void* __restrict__ adj)
{
    const int i    = blockIdx.x;
    const int tid  = threadIdx.x;
    const int lane = tid & 31;
    const int wid  = tid >> 5;
    const uint8_t* u8 = (const uint8_t*)adj;

    int fmt;
    if (u8[(size_t)N_NODES + 1] == 1)            fmt = 0;
    else if (u8[4 * ((size_t)N_NODES + 1)] == 1) fmt = 1;
    else                                         fmt = 2;

    uint32_t mask = 0;
    #pragma unroll
    for (int r = 0; r < 8; r++) {
        const int cbase = (r * 128 + tid) * 4;
        uint32_t p0, p1, p2, p3;
        if (fmt == 2) {
            float4 v = *(const float4*)((const float*)adj + (size_t)i * N_NODES + cbase);
            p0 = v.x != 0.f; p1 = v.y != 0.f; p2 = v.z != 0.f; p3 = v.w != 0.f;
        } else if (fmt == 1) {
            int4 v = *(const int4*)((const int*)adj + (size_t)i * N_NODES + cbase);
            p0 = v.x != 0; p1 = v.y != 0; p2 = v.z != 0; p3 = v.w != 0;
        } else {
            uint32_t w = *(const uint32_t*)(u8 + (size_t)i * N_NODES + cbase);
            p0 = (w & 0x000000FFu) != 0;
            p1 = (w & 0x0000FF00u) != 0;
            p2 = (w & 0x00FF0000u) != 0;
            p3 = (w & 0xFF000000u) != 0;
        }
        mask |= (p0 << (r * 4)) | (p1 << (r * 4 + 1)) |
                (p2 << (r * 4 + 2)) | (p3 << (r * 4 + 3));
    }
    const int cnt = __popc(mask);

    int incl = cnt;
    #pragma unroll
    for (int o = 1; o < 32; o <<= 1) {
        int t = __shfl_up_sync(0xFFFFFFFFu, incl, o);
        if (lane >= o) incl += t;
    }
    __shared__ int wsum[4];
    if (lane == 31) wsum[wid] = incl;
    __syncthreads();
    int wpre = 0, total = 0;
    #pragma unroll
    for (int wq = 0; wq < 4; wq++) {
        int t = wsum[wq];
        if (wq < wid) wpre += t;
        total += t;
    }
    if (tid == 0) g_deg[i] = (total > MAXDEG) ? MAXDEG : total;

    int base = wpre + (incl - cnt);
    int* out = g_nbr + (size_t)i * MAXDEG;
    #pragma unroll
    for (int r = 0; r < 8; r++) {
        const int cbase = (r * 128 + tid) * 4;
        #pragma unroll
        for (int q = 0; q < 4; q++) {
            if ((mask >> (r * 4 + q)) & 1u) {
                if (base < MAXDEG) out[base] = cbase + q;
                base++;
            }
        }
    }
}

// ---------------------------------------------------------------------------
// K2: GEMM1 h1 = x @ W1 + fused es1/ed1 epilogue. (round-3, unchanged)
// ---------------------------------------------------------------------------
__global__ __launch_bounds__(256) void k_gemm1(const float* __restrict__ X,
                                               const float* __restrict__ W,
                                               const float* __restrict__ a_src,
                                               const float* __restrict__ a_dst)
{
    __shared__ float As[32][33];
    __shared__ float Bs[32][64];

    const int tid = threadIdx.x;
    const int tx  = tid & 15;
    const int ty  = tid >> 4;
    const int m0  = blockIdx.x * 32;

    float acc[2][4] = {};

    for (int kt = 0; kt < F_IN; kt += 32) {
        {
            int r  = tid >> 3;
            int c4 = tid & 7;
            float4 v = *(const float4*)(X + (size_t)(m0 + r) * F_IN + kt + c4 * 4);
            As[c4 * 4 + 0][r] = v.x;
            As[c4 * 4 + 1][r] = v.y;
            As[c4 * 4 + 2][r] = v.z;
            As[c4 * 4 + 3][r] = v.w;
        }
        #pragma unroll
        for (int it = 0; it < 2; it++) {
            int id = tid + it * 256;
            int r  = id >> 4;
            int c4 = id & 15;
            *(float4*)(&Bs[r][c4 * 4]) =
                *(const float4*)(W + (size_t)(kt + r) * HD1 + c4 * 4);
        }
        __syncthreads();
        #pragma unroll
        for (int k = 0; k < 32; k++) {
            float a0 = As[k][ty * 2 + 0];
            float a1 = As[k][ty * 2 + 1];
            float4 b = *(const float4*)(&Bs[k][tx * 4]);
            acc[0][0] += a0 * b.x; acc[0][1] += a0 * b.y;
            acc[0][2] += a0 * b.z; acc[0][3] += a0 * b.w;
            acc[1][0] += a1 * b.x; acc[1][1] += a1 * b.y;
            acc[1][2] += a1 * b.z; acc[1][3] += a1 * b.w;
        }
        __syncthreads();
    }

    #pragma unroll
    for (int u = 0; u < 2; u++) {
        float4 v = make_float4(acc[u][0], acc[u][1], acc[u][2], acc[u][3]);
        *(float4*)(g_h1 + (size_t)(m0 + ty * 2 + u) * HD1 + tx * 4) = v;
    }

    float4 ws = *(const float4*)(a_src + tx * 4);
    float4 wd = *(const float4*)(a_dst + tx * 4);
    float s0 = acc[0][0]*ws.x + acc[0][1]*ws.y + acc[0][2]*ws.z + acc[0][3]*ws.w;
    float s1 = acc[1][0]*ws.x + acc[1][1]*ws.y + acc[1][2]*ws.z + acc[1][3]*ws.w;
    float d0 = acc[0][0]*wd.x + acc[0][1]*wd.y + acc[0][2]*wd.z + acc[0][3]*wd.w;
    float d1 = acc[1][0]*wd.x + acc[1][1]*wd.y + acc[1][2]*wd.z + acc[1][3]*wd.w;
    s0 += __shfl_xor_sync(0xFFFFFFFFu, s0, 1);
    s1 += __shfl_xor_sync(0xFFFFFFFFu, s1, 1);
    d0 += __shfl_xor_sync(0xFFFFFFFFu, d0, 1);
    d1 += __shfl_xor_sync(0xFFFFFFFFu, d1, 1);
    if ((tx & 1) == 0) {
        int h = tx >> 1;
        g_es1[(m0 + ty * 2 + 0) * NH1 + h] = s0;
        g_es1[(m0 + ty * 2 + 1) * NH1 + h] = s1;
        g_ed1[(m0 + ty * 2 + 0) * NH1 + h] = d0;
        g_ed1[(m0 + ty * 2 + 1) * NH1 + h] = d1;
    }
}

// ---------------------------------------------------------------------------
// K3: layer-1 attention + ELU + fused layer-2 projection & scores.
// 1 block/row, 64 threads. (round-3, unchanged)
// ---------------------------------------------------------------------------
__global__ __launch_bounds__(64) void k_attn1(const float* __restrict__ W2,
                                              const float* __restrict__ a2_src,
                                              const float* __restrict__ a2_dst)
{
    const int i   = blockIdx.x;
    const int tid = threadIdx.x;
    const int deg = g_deg[i];

    __shared__ int   snbr[MAXDEG];
    __shared__ float ew[MAXDEG * NH1];
    __shared__ float sm[NH1], ss[NH1], sesi[NH1];
    __shared__ float sa1[HD1];

    for (int j = tid; j < deg; j += 64)
        snbr[j] = g_nbr[(size_t)i * MAXDEG + j];
    if (tid < NH1) sesi[tid] = g_es1[i * NH1 + tid];
    __syncthreads();

    const int tot = deg * NH1;
    for (int idx = tid; idx < tot; idx += 64) {
        int j = idx >> 3, h = idx & 7;
        float e = sesi[h] + g_ed1[snbr[j] * NH1 + h];
        e = (e > 0.f) ? e : 0.2f * e;
        ew[idx] = e;
    }
    __syncthreads();

    if (tid < NH1) {
        float m = -1e30f;
        for (int j = 0; j < deg; j++) m = fmaxf(m, ew[j * NH1 + tid]);
        float s = 0.f;
        for (int j = 0; j < deg; j++) s += __expf(ew[j * NH1 + tid] - m);
        sm[tid] = m;
        ss[tid] = 1.f / s;
    }
    __syncthreads();

    for (int idx = tid; idx < tot; idx += 64) {
        int h = idx & 7;
        ew[idx] = __expf(ew[idx] - sm[h]) * ss[h];
    }
    __syncthreads();

    {
        const int h = tid >> 3;
        float a0 = 0.f, a1 = 0.f, a2 = 0.f, a3 = 0.f;
        int j = 0;
        for (; j + 4 <= deg; j += 4) {
            a0 += ew[(j+0) * NH1 + h] * g_h1[(size_t)snbr[j+0] * HD1 + tid];
            a1 += ew[(j+1) * NH1 + h] * g_h1[(size_t)snbr[j+1] * HD1 + tid];
            a2 += ew[(j+2) * NH1 + h] * g_h1[(size_t)snbr[j+2] * HD1 + tid];
            a3 += ew[(j+3) * NH1 + h] * g_h1[(size_t)snbr[j+3] * HD1 + tid];
        }
        for (; j < deg; j++)
            a0 += ew[j * NH1 + h] * g_h1[(size_t)snbr[j] * HD1 + tid];
        float acc = (a0 + a1) + (a2 + a3);
        acc = (acc > 0.f) ? acc : expm1f(acc);   // ELU
        sa1[tid] = acc;
    }
    __syncthreads();

    if (tid < C2) {
        float v = 0.f;
        #pragma unroll 8
        for (int k = 0; k < HD1; k++)
            v += sa1[k] * __ldg(&W2[k * C2 + tid]);
        g_h2[(size_t)i * C2 + tid] = v;

        float s = v * a2_src[tid];
        float d = v * a2_dst[tid];
        #pragma unroll
        for (int o = 8; o >= 1; o >>= 1) {
            s += __shfl_xor_sync(0x0000FFFFu, s, o);
            d += __shfl_xor_sync(0x0000FFFFu, d, o);
        }
        if (tid == 0) {
            g_es2[i] = s;
            g_ed2[i] = d;
        }
    }
}

// ---------------------------------------------------------------------------
// K4: layer-2 sparse attention. 8 rows per 256-thread block, 1 warp/row.
// Gather: 4 lanes per neighbor, float4 loads -> full-warp utilization,
// 8 neighbors in flight per pass; 3-step shfl-xor cross-group reduction.
// ---------------------------------------------------------------------------
__global__ __launch_bounds__(256) void k_attn2(float* __restrict__ out)
{
    const int w    = threadIdx.x >> 5;
    const int lane = threadIdx.x & 31;
    const int i    = blockIdx.x * 8 + w;
    const int deg  = g_deg[i];

    __shared__ int   snbr[8][MAXDEG];
    __shared__ float ew  [8][MAXDEG];

    for (int j = lane; j < deg; j += 32)
        snbr[w][j] = g_nbr[(size_t)i * MAXDEG + j];
    __syncwarp();

    const float esi = g_es2[i];
    float mloc = -1e30f;
    for (int j = lane; j < deg; j += 32) {
        float e = esi + g_ed2[snbr[w][j]];
        e = (e > 0.f) ? e : 0.2f * e;
        ew[w][j] = e;
        mloc = fmaxf(mloc, e);
    }
    #pragma unroll
    for (int o = 16; o >= 1; o >>= 1)
        mloc = fmaxf(mloc, __shfl_xor_sync(0xFFFFFFFFu, mloc, o));
    __syncwarp();

    float sloc = 0.f;
    for (int j = lane; j < deg; j += 32) {
        float v = __expf(ew[w][j] - mloc);
        ew[w][j] = v;
        sloc += v;
    }
    #pragma unroll
    for (int o = 16; o >= 1; o >>= 1)
        sloc += __shfl_xor_sync(0xFFFFFFFFu, sloc, o);
    const float inv = 1.f / sloc;
    __syncwarp();

    // cooperative float4 gather: neighbor group g = lane>>2, col chunk = lane&3
    const int g  = lane >> 2;
    const int c4 = lane & 3;
    float4 acc = make_float4(0.f, 0.f, 0.f, 0.f);
    for (int base = 0; base < deg; base += 8) {
        int j = base + g;
        if (j < deg) {
            float  wt = ew[w][j];
            float4 v  = *(const float4*)(g_h2 + (size_t)snbr[w][j] * C2 + c4 * 4);
            acc.x += wt * v.x;
            acc.y += wt * v.y;
            acc.z += wt * v.z;
            acc.w += wt * v.w;
        }
    }
    // reduce across the 8 neighbor groups (lane&3 preserved by xor 4/8/16)
    #pragma unroll
    for (int o = 4; o <= 16; o <<= 1) {
        acc.x += __shfl_xor_sync(0xFFFFFFFFu, acc.x, o);
        acc.y += __shfl_xor_sync(0xFFFFFFFFu, acc.y, o);
        acc.z += __shfl_xor_sync(0xFFFFFFFFu, acc.z, o);
        acc.w += __shfl_xor_sync(0xFFFFFFFFu, acc.w, o);
    }
    if (lane < 4) {
        float4 r = make_float4(acc.x * inv, acc.y * inv, acc.z * inv, acc.w * inv);
        *(float4*)(out + (size_t)i * C2 + lane * 4) = r;
    }
}

// ---------------------------------------------------------------------------
extern "C" void kernel_launch(void* const* d_in, const int* in_sizes, int n_in,
                              void* d_out, int out_size)
{
    const float* x      = (const float*)d_in[0];
    const void*  adj    = d_in[1];
    const float* W1     = (const float*)d_in[2];
    const float* a1_src = (const float*)d_in[3];
    const float* a1_dst = (const float*)d_in[4];
    const float* W2     = (const float*)d_in[5];
    const float* a2_src = (const float*)d_in[6];
    const float* a2_dst = (const float*)d_in[7];
    float* out = (float*)d_out;

    k_scan <<<N_NODES, 128>>>(adj);
    k_gemm1<<<N_NODES / 32, 256>>>(x, W1, a1_src, a1_dst);
    k_attn1<<<N_NODES, 64>>>(W2, a2_src, a2_dst);
    k_attn2<<<N_NODES / 8, 256>>>(out);
}